// round 12
// baseline (speedup 1.0000x reference)
#include <cuda_runtime.h>
#include <math.h>

#define BB    1024   // batch
#define DD    1024   // embed dim
#define NE    128    // num experts / N
#define PT    28     // PT_DEPTH
#define KSEL  32     // k-1 (softmax'd top count)
#define BPB   128    // batch rows per k_out block
#define JC    16     // j-chunks for std partials
#define JW    (DD / JC)  // 64 j per chunk

// ---------------- scratch (device globals; no allocation allowed) ----------
__device__ float g_h[PT * DD];                     // silu(t*w1+b1) per step
__device__ __align__(16) float g_te[PT * DD];      // t_embed per unique step
__device__ float g_clean[PT * NE];                 // clean logits per step
__device__ float g_std[PT * NE];                   // noise std per step
__device__ float g_sp[PT * JC * NE];               // std partial dots
__device__ float g_gates[BB * NE];                 // per-row gates
__device__ int   g_ts[BB];                         // decoded timesteps
__device__ int   g_step;                           // timestep[0]

// ---------------- 0+1) fused: decode timesteps | h = silu ------------------
// Blocks 0..27: h[s,i] = silu(s*w1[i]+b1[i]).  Block 28: decode timestep
// buffer (int32 OR int64). If int64: words are [t0,0,t1,0,...] -> all odd
// words 0. If int32: odd words random in [0,28); all-zero impossible.
__global__ __launch_bounds__(1024) void k_front(const int* __restrict__ raw,
                                                const float* __restrict__ w1,
                                                const float* __restrict__ b1) {
    __shared__ int is32;
    int blk = blockIdx.x;
    int tid = threadIdx.x;
    if (blk < PT) {
        float x = (float)blk * w1[tid] + b1[tid];
        g_h[blk * DD + tid] = x / (1.0f + expf(-x));   // silu
    } else {
        if (tid == 0) is32 = 0;
        __syncthreads();
        int w = raw[tid];              // words 0..1023: valid either way
        if ((tid & 1) && w != 0) atomicOr(&is32, 1);
        __syncthreads();
        int v = is32 ? raw[tid] : raw[2 * tid];
        g_ts[tid] = v;
        if (tid == 0) g_step = v;
    }
}

// ---------------- 2) t_embed[s,j] = dot(h[s,:], w2[j,:]) + b2[j] -----------
// 4 j-columns per block (grid 256): w2 rows staged in smem (16KB, coalesced,
// read once from DRAM). g_h read from L2 on the first j-pass, L1 on the
// other three (112KB fits 228KB L1) -> L2 traffic 114MB -> 29MB.
// 4 warps x 7 steps each; 7 accs/lane keeps loads front-batched.
__global__ __launch_bounds__(128) void k_embed(const float* __restrict__ w2,
                                               const float* __restrict__ b2) {
    __shared__ float sw[4 * DD];
    int j0 = blockIdx.x * 4;
    int t = threadIdx.x;
    int lane = t & 31, w = t >> 5;
    const float* w2base = w2 + (size_t)j0 * DD;
#pragma unroll
    for (int i = t; i < 4 * DD; i += 128) sw[i] = w2base[i];
    __syncthreads();
    int s0 = w * 7;                    // warp w handles steps s0..s0+6
#pragma unroll
    for (int jj = 0; jj < 4; jj++) {
        const float* swj = sw + jj * DD;
        float acc[7];
#pragma unroll
        for (int q = 0; q < 7; q++) acc[q] = 0.0f;
        for (int i = lane; i < DD; i += 32) {
            float wv = swj[i];
#pragma unroll
            for (int q = 0; q < 7; q++) acc[q] += g_h[(s0 + q) * DD + i] * wv;
        }
#pragma unroll
        for (int q = 0; q < 7; q++) {
#pragma unroll
            for (int o = 16; o > 0; o >>= 1)
                acc[q] += __shfl_xor_sync(0xffffffffu, acc[q], o);
        }
        if (lane == 0) {
            float bb = b2[j0 + jj];
#pragma unroll
            for (int q = 0; q < 7; q++) g_te[(s0 + q) * DD + (j0 + jj)] = acc[q] + bb;
        }
    }
}

// ---------------- 3) fused clean | std partials ----------------------------
// grid (PT, NE+JC). y<NE: clean[s,n] block-per-(s,n) reduction (coalesced,
// L2-resident). y>=NE: std partial g_sp[s,jc,n], thread=n so w_noise
// coalesced. Deterministic (no float atomics).
__global__ __launch_bounds__(128) void k_mid(const float* __restrict__ gate_w,
                                             const float* __restrict__ gate_b,
                                             const float* __restrict__ w_noise) {
    __shared__ float red[4];
    __shared__ float ste[JW];
    int s = blockIdx.x;
    int y = blockIdx.y;
    int t = threadIdx.x;
    if (y < NE) {
        int n = y;
        int lane = t & 31;
        const float* gw = gate_w + (size_t)n * (DD + 1);
        const float* te = g_te + (size_t)s * DD;
        float a = 0.0f;
#pragma unroll
        for (int j = t; j < DD; j += 128) a += te[j] * gw[j];
#pragma unroll
        for (int o = 16; o > 0; o >>= 1) a += __shfl_xor_sync(0xffffffffu, a, o);
        if (lane == 0) red[t >> 5] = a;
        __syncthreads();
        if (t == 0) {
            float sum = red[0] + red[1] + red[2] + red[3];
            g_clean[s * NE + n] = sum + (float)g_step * gw[DD] + gate_b[n];
        }
    } else {
        int jc = y - NE;
        int n = t;
        if (n < JW) ste[n] = g_te[s * DD + jc * JW + n];
        __syncthreads();
        const float* wn = w_noise + (size_t)(jc * JW) * NE + n;
        float as = 0.0f;
#pragma unroll 8
        for (int j = 0; j < JW; j++) as += ste[j] * wn[(size_t)j * NE];
        g_sp[(s * JC + jc) * NE + n] = as;
    }
}

// ---------------- 3c) std finalize: softplus(sum partials) + eps -----------
__global__ __launch_bounds__(NE) void k_stdf() {
    int s = blockIdx.x, n = threadIdx.x;
    float as = 0.0f;
#pragma unroll
    for (int jc = 0; jc < JC; jc++) as += g_sp[(s * JC + jc) * NE + n];
    float sp = (as > 20.0f) ? as : log1pf(expf(as));   // softplus
    g_std[s * NE + n] = sp + 0.01f;                    // NOISE_EPS
}

// ---------------- 4) per-row noisy top-32 softmax gates --------------------
// Exact-rank selection matches jax.lax.top_k's stable tie-break.
__global__ __launch_bounds__(NE) void k_topk(const float* __restrict__ noise) {
    __shared__ float sv[NE];
    __shared__ float red[NE];
    __shared__ float smax;
    int b = blockIdx.x, n = threadIdx.x;
    int s = g_ts[b];
    float v = g_clean[s * NE + n] + noise[(size_t)b * NE + n] * g_std[s * NE + n];
    sv[n] = v;
    __syncthreads();
    int rank = 0;
#pragma unroll 8
    for (int m = 0; m < NE; m++) {
        float u = sv[m];
        rank += (u > v) || (u == v && m < n);
    }
    if (rank == 0) smax = v;   // unique by tie-break
    __syncthreads();
    float e = (rank < KSEL) ? expf(v - smax) : 0.0f;
    red[n] = e;
    __syncthreads();
#pragma unroll
    for (int o = NE / 2; o > 0; o >>= 1) {
        if (n < o) red[n] += red[n + o];
        __syncthreads();
    }
    g_gates[b * NE + n] = e / red[0];
}

// ---------------- 5+6) fused out | t_embed gather --------------------------
// x<NE: out[b,n,:] = gates[b,n]*prompts[step,n,:] for a 128-batch slab.
// Prompt row in registers; 128 streaming stores/thread (deep MLP,
// evict-first). x==NE: t_embed output rows for the same batch slab.
__global__ __launch_bounds__(256) void k_out(const float* __restrict__ prompt,
                                             float* __restrict__ out,
                                             int do_temb) {
    __shared__ float sg[BPB];
    int n = blockIdx.x;
    int b0 = blockIdx.y * BPB;
    int t = threadIdx.x;
    if (n == NE) {
        if (!do_temb) return;
        float4* ob = (float4*)(out + (size_t)BB * NE * DD);
        for (int bi = 0; bi < BPB; bi++) {
            int b = b0 + bi;
            int s = g_ts[b];
            float4 v = ((const float4*)(g_te + (size_t)s * DD))[t];
            __stcs(ob + (size_t)b * (DD / 4) + t, v);
        }
        return;
    }
    if (t < BPB) sg[t] = g_gates[(size_t)(b0 + t) * NE + n];
    float4 p = ((const float4*)(prompt + ((size_t)(g_step * NE + n)) * DD))[t];
    __syncthreads();
    float4* ob = (float4*)out + ((size_t)b0 * NE + n) * (DD / 4) + t;
#pragma unroll 16
    for (int b = 0; b < BPB; b++) {
        float g = sg[b];
        float4 o;
        o.x = g * p.x; o.y = g * p.y; o.z = g * p.z; o.w = g * p.w;
        __stcs(ob, o);
        ob += (size_t)NE * (DD / 4);
    }
}

// ---------------- launch ---------------------------------------------------
extern "C" void kernel_launch(void* const* d_in, const int* in_sizes, int n_in,
                              void* d_out, int out_size) {
    const float* prompt  = (const float*)d_in[0];  // [28,128,1024]
    const float* w1      = (const float*)d_in[1];  // [1024,1]
    const float* b1      = (const float*)d_in[2];  // [1024]
    const float* w2      = (const float*)d_in[3];  // [1024,1024]
    const float* b2      = (const float*)d_in[4];  // [1024]
    const float* gate_w  = (const float*)d_in[5];  // [128,1025]
    const float* gate_b  = (const float*)d_in[6];  // [128]
    const float* w_noise = (const float*)d_in[7];  // [1024,128]
    const float* noise   = (const float*)d_in[8];  // [1024,128]
    const int*   tsraw   = (const int*)d_in[9];    // int32 or int64, detected
    float* out = (float*)d_out;

    k_front<<<PT + 1, 1024>>>(tsraw, w1, b1);
    k_embed<<<DD / 4, 128>>>(w2, b2);
    dim3 gm(PT, NE + JC);
    k_mid<<<gm, 128>>>(gate_w, gate_b, w_noise);
    k_stdf<<<PT, NE>>>();
    k_topk<<<BB, NE>>>(noise);

    size_t main_sz = (size_t)BB * NE * DD;
    int do_temb = ((size_t)out_size >= main_sz + (size_t)BB * DD) ? 1 : 0;
    dim3 go(NE + 1, BB / BPB);
    k_out<<<go, 256>>>(prompt, out, do_temb);
}

// round 13
// speedup vs baseline: 1.2083x; 1.2083x over previous
#include <cuda_runtime.h>
#include <math.h>

#define BB    1024   // batch
#define DD    1024   // embed dim
#define NE    128    // num experts / N
#define PT    28     // PT_DEPTH
#define KSEL  32     // k-1 (softmax'd top count)
#define BPB   128    // batch rows per k_out block
#define JC    16     // j-chunks for std partials
#define JW    (DD / JC)  // 64 j per chunk

// ---------------- scratch (device globals; no allocation allowed) ----------
__device__ float g_h[PT * DD];                     // silu(t*w1+b1) per step
__device__ __align__(16) float g_te[PT * DD];      // t_embed per unique step
__device__ float g_clean[PT * NE];                 // clean logits per step
__device__ float g_sp[PT * JC * NE];               // std partial dots
__device__ float g_gates[BB * NE];                 // per-row gates
__device__ int   g_ts[BB];                         // decoded timesteps
__device__ int   g_step;                           // timestep[0]

// ---------------- 0) decode timestep buffer (int32 OR int64) ---------------
// If int64: first 1024 words = [t0,0,t1,0,...] -> all odd words 0.
// If int32: odd words are random in [0,28); all-zero is impossible.
__global__ void k_decode(const int* __restrict__ raw) {
    __shared__ int is32;
    int tid = threadIdx.x;
    if (tid == 0) is32 = 0;
    __syncthreads();
    int w = raw[tid];                 // words 0..1023: valid either way
    if ((tid & 1) && w != 0) atomicOr(&is32, 1);
    __syncthreads();
    int v = is32 ? raw[tid] : raw[2 * tid];
    g_ts[tid] = v;
    if (tid == 0) g_step = v;
}

// ---------------- 1) h[s,i] = silu(s * w1[i] + b1[i]) ----------------------
__global__ void k_h(const float* __restrict__ w1, const float* __restrict__ b1) {
    int s = blockIdx.x, i = threadIdx.x;
    float x = (float)s * w1[i] + b1[i];
    g_h[s * DD + i] = x / (1.0f + expf(-x));       // silu
}

// ---------------- 2) t_embed[s,j] = dot(h[s,:], w2[j,:]) + b2[j] -----------
// Block per j (1024 blocks). w2 row staged in smem once (coalesced, read
// exactly once from DRAM). 4 warps x 7 steps each: only 7 accs/lane so
// ptxas keeps loads batched; g_h (112KB) hits L1/L2.
__global__ __launch_bounds__(128) void k_embed(const float* __restrict__ w2,
                                               const float* __restrict__ b2) {
    __shared__ float sw[DD];
    int j = blockIdx.x;
    int t = threadIdx.x;
    int lane = t & 31, w = t >> 5;
    const float* w2row = w2 + (size_t)j * DD;
#pragma unroll
    for (int i = t; i < DD; i += 128) sw[i] = w2row[i];
    __syncthreads();
    int s0 = w * 7;                   // warp w handles steps s0..s0+6
    float acc[7];
#pragma unroll
    for (int q = 0; q < 7; q++) acc[q] = 0.0f;
    for (int i = lane; i < DD; i += 32) {
        float wv = sw[i];
#pragma unroll
        for (int q = 0; q < 7; q++) acc[q] += g_h[(s0 + q) * DD + i] * wv;
    }
#pragma unroll
    for (int q = 0; q < 7; q++) {
#pragma unroll
        for (int o = 16; o > 0; o >>= 1)
            acc[q] += __shfl_xor_sync(0xffffffffu, acc[q], o);
    }
    if (lane == 0) {
        float bb = b2[j];
#pragma unroll
        for (int q = 0; q < 7; q++) g_te[(s0 + q) * DD + j] = acc[q] + bb;
    }
}

// ---------------- 3a) clean[s,n] = te[s,:].gate_w[n,:D] + step*gw[D] + b ---
// Block per (s,n) = 3584 blocks: latency hidden by sheer parallelism.
// Both reads j-contiguous -> coalesced; te + gate_w are L2-resident.
__global__ __launch_bounds__(128) void k_clean(const float* __restrict__ gate_w,
                                               const float* __restrict__ gate_b) {
    __shared__ float red[4];
    int s = blockIdx.x, n = blockIdx.y;
    int t = threadIdx.x;
    int lane = t & 31;
    const float* gw = gate_w + (size_t)n * (DD + 1);
    const float* te = g_te + (size_t)s * DD;
    float a = 0.0f;
#pragma unroll
    for (int j = t; j < DD; j += 128) a += te[j] * gw[j];
#pragma unroll
    for (int o = 16; o > 0; o >>= 1) a += __shfl_xor_sync(0xffffffffu, a, o);
    if (lane == 0) red[t >> 5] = a;
    __syncthreads();
    if (t == 0) {
        float sum = red[0] + red[1] + red[2] + red[3];
        g_clean[s * NE + n] = sum + (float)g_step * gw[DD] + gate_b[n];
    }
}

// ---------------- 3b) std partials: g_sp[s,jc,n] ---------------------------
// Block per (s, j-chunk); thread = n -> w_noise[j*NE+n] coalesced.
// Deterministic two-stage reduction (no float atomics).
__global__ __launch_bounds__(NE) void k_stdp(const float* __restrict__ w_noise) {
    __shared__ float ste[JW];
    int s = blockIdx.x, jc = blockIdx.y;
    int n = threadIdx.x;
    if (n < JW) ste[n] = g_te[s * DD + jc * JW + n];
    __syncthreads();
    const float* wn = w_noise + (size_t)(jc * JW) * NE + n;
    float as = 0.0f;
#pragma unroll 8
    for (int j = 0; j < JW; j++) as += ste[j] * wn[(size_t)j * NE];
    g_sp[(s * JC + jc) * NE + n] = as;
}

// ---------------- 4) per-row noisy top-32 softmax gates --------------------
// std finalize (softplus of 16 summed partials) fused in: same summation
// order as the old k_stdf -> bit-identical, kills the 4us straggler launch.
// Exact-rank selection matches jax.lax.top_k's stable tie-break.
__global__ __launch_bounds__(NE) void k_topk(const float* __restrict__ noise) {
    __shared__ float sv[NE];
    __shared__ float red[NE];
    __shared__ float smax;
    int b = blockIdx.x, n = threadIdx.x;
    int s = g_ts[b];
    float as = 0.0f;
#pragma unroll
    for (int jc = 0; jc < JC; jc++) as += g_sp[(s * JC + jc) * NE + n];
    float sp = (as > 20.0f) ? as : log1pf(expf(as));   // softplus
    float stdv = sp + 0.01f;                           // NOISE_EPS
    float v = g_clean[s * NE + n] + noise[(size_t)b * NE + n] * stdv;
    sv[n] = v;
    __syncthreads();
    int rank = 0;
#pragma unroll 8
    for (int m = 0; m < NE; m++) {
        float u = sv[m];
        rank += (u > v) || (u == v && m < n);
    }
    if (rank == 0) smax = v;   // unique by tie-break
    __syncthreads();
    float e = (rank < KSEL) ? expf(v - smax) : 0.0f;
    red[n] = e;
    __syncthreads();
#pragma unroll
    for (int o = NE / 2; o > 0; o >>= 1) {
        if (n < o) red[n] += red[n + o];
        __syncthreads();
    }
    g_gates[b * NE + n] = e / red[0];
}

// ---------------- 5) out[b,n,:] = gates[b,n] * prompts[step,n,:] -----------
// One block per (n, 128-batch-slab). Prompt row lives in registers; 128
// streaming stores per thread (deep MLP, evict-first so the 512MB write
// stream doesn't thrash L2). Prompt L2 read traffic: 512MB -> 4MB.
__global__ __launch_bounds__(256) void k_out(const float* __restrict__ prompt,
                                             float* __restrict__ out) {
    __shared__ float sg[BPB];
    int n = blockIdx.x;
    int b0 = blockIdx.y * BPB;
    int t = threadIdx.x;
    if (t < BPB) sg[t] = g_gates[(size_t)(b0 + t) * NE + n];
    float4 p = ((const float4*)(prompt + ((size_t)(g_step * NE + n)) * DD))[t];
    __syncthreads();
    float4* ob = (float4*)out + ((size_t)b0 * NE + n) * (DD / 4) + t;
#pragma unroll 16
    for (int b = 0; b < BPB; b++) {
        float g = sg[b];
        float4 o;
        o.x = g * p.x; o.y = g * p.y; o.z = g * p.z; o.w = g * p.w;
        __stcs(ob, o);
        ob += (size_t)NE * (DD / 4);
    }
}

// ---------------- 6) t_embed output: gather dedup'd rows -------------------
__global__ __launch_bounds__(256) void k_temb(float* __restrict__ out) {
    int b = blockIdx.x, t = threadIdx.x;
    int s = g_ts[b];
    float4 v = ((const float4*)(g_te + (size_t)s * DD))[t];
    __stcs((float4*)out + (size_t)b * (DD / 4) + t, v);
}

// ---------------- launch ---------------------------------------------------
extern "C" void kernel_launch(void* const* d_in, const int* in_sizes, int n_in,
                              void* d_out, int out_size) {
    const float* prompt  = (const float*)d_in[0];  // [28,128,1024]
    const float* w1      = (const float*)d_in[1];  // [1024,1]
    const float* b1      = (const float*)d_in[2];  // [1024]
    const float* w2      = (const float*)d_in[3];  // [1024,1024]
    const float* b2      = (const float*)d_in[4];  // [1024]
    const float* gate_w  = (const float*)d_in[5];  // [128,1025]
    const float* gate_b  = (const float*)d_in[6];  // [128]
    const float* w_noise = (const float*)d_in[7];  // [1024,128]
    const float* noise   = (const float*)d_in[8];  // [1024,128]
    const int*   tsraw   = (const int*)d_in[9];    // int32 or int64, detected
    float* out = (float*)d_out;

    k_decode<<<1, BB>>>(tsraw);
    k_h<<<PT, DD>>>(w1, b1);
    k_embed<<<DD, 128>>>(w2, b2);
    dim3 gc(PT, NE);
    k_clean<<<gc, 128>>>(gate_w, gate_b);
    dim3 gsp(PT, JC);
    k_stdp<<<gsp, NE>>>(w_noise);
    k_topk<<<BB, NE>>>(noise);
    dim3 go(NE, BB / BPB);
    k_out<<<go, 256>>>(prompt, out);

    size_t main_sz = (size_t)BB * NE * DD;
    if ((size_t)out_size >= main_sz + (size_t)BB * DD)
        k_temb<<<BB, 256>>>(out + main_sz);
}